// round 1
// baseline (speedup 1.0000x reference)
#include <cuda_runtime.h>

#define SEQ    512
#define BATCH  64
#define DIM    512
#define MAXLEN 512
#define NWORDS (SEQ/32)   // 16 bitmap words per (b,u) row

// 2 MB bitmap: bit v of row (b*MAXLEN+u) set iff some edge hits (b,u,v).
__device__ unsigned g_maskbits[BATCH * MAXLEN * NWORDS];

__global__ void clear_mask_kernel() {
    int i = blockIdx.x * blockDim.x + threadIdx.x;
    if (i < BATCH * MAXLEN * NWORDS) g_maskbits[i] = 0u;
}

__global__ void build_mask_kernel(const int* __restrict__ eb,
                                  const int* __restrict__ eu,
                                  const int* __restrict__ ev, int E) {
    int i = blockIdx.x * blockDim.x + threadIdx.x;
    if (i >= E) return;
    int b = eb[i], u = eu[i], v = ev[i];
    atomicOr(&g_maskbits[(b * MAXLEN + u) * NWORDS + (v >> 5)], 1u << (v & 31));
}

// One block computes scale[utile:utile+32, b, 0:512] (full s-row per u),
// then each warp (owning 4 complete rows) does softmax stats + masked
// renormalization + writes the final output row (zeros off-mask).
__global__ __launch_bounds__(256, 2)
void gemm_softmax_kernel(const float* __restrict__ Mm,   // (SEQ, BATCH, DIM)
                         const float* __restrict__ Wm,   // (MAXLEN, DIM)
                         float* __restrict__ out) {      // (BATCH, MAXLEN, SEQ)
    __shared__ float As[8][32];    // [d][u]
    __shared__ float Bs[8][512];   // [d][s]

    const int tid   = threadIdx.x;
    const int tx    = tid & 31;    // s-fragment lane
    const int ty    = tid >> 5;    // warp id = u-fragment group (0..7)
    const int b     = blockIdx.y;
    const int utile = blockIdx.x * 32;

    float acc[4][16];
    #pragma unroll
    for (int i = 0; i < 4; i++)
        #pragma unroll
        for (int j = 0; j < 16; j++) acc[i][j] = 0.f;

    const int brow = tid >> 1;          // 0..127
    const int bd0  = (tid & 1) * 4;     // 0 or 4

    for (int kt = 0; kt < DIM; kt += 8) {
        // A tile: W[utile+u, kt..kt+7], 32x8
        if (tid < 64) {
            int u  = tid >> 1;
            int d0 = (tid & 1) * 4;
            float4 av = *(const float4*)&Wm[(utile + u) * DIM + kt + d0];
            As[d0 + 0][u] = av.x; As[d0 + 1][u] = av.y;
            As[d0 + 2][u] = av.z; As[d0 + 3][u] = av.w;
        }
        // B tile: M[s, b, kt..kt+7], 512x8
        #pragma unroll
        for (int r = 0; r < 4; r++) {
            int s = brow + r * 128;
            float4 bv = *(const float4*)&Mm[((size_t)s * BATCH + b) * DIM + kt + bd0];
            Bs[bd0 + 0][s] = bv.x; Bs[bd0 + 1][s] = bv.y;
            Bs[bd0 + 2][s] = bv.z; Bs[bd0 + 3][s] = bv.w;
        }
        __syncthreads();
        #pragma unroll
        for (int k = 0; k < 8; k++) {
            float4 a = *(const float4*)&As[k][ty * 4];
            float av[4] = {a.x, a.y, a.z, a.w};
            #pragma unroll
            for (int g = 0; g < 4; g++) {
                float4 bv = *(const float4*)&Bs[k][tx * 4 + g * 128];
                #pragma unroll
                for (int i = 0; i < 4; i++) {
                    acc[i][g * 4 + 0] += av[i] * bv.x;
                    acc[i][g * 4 + 1] += av[i] * bv.y;
                    acc[i][g * 4 + 2] += av[i] * bv.z;
                    acc[i][g * 4 + 3] += av[i] * bv.w;
                }
            }
        }
        __syncthreads();
    }

    // Epilogue: warp ty owns full rows u = utile + ty*4 + i (i=0..3).
    // Lane tx holds s = tx*4 + j + g*128 (j=0..3, g=0..3).
    #pragma unroll
    for (int i = 0; i < 4; i++) {
        const int u = utile + ty * 4 + i;
        const int r = b * MAXLEN + u;

        // row max (16 local values + warp reduce)
        float m = -3.402823466e38f;
        #pragma unroll
        for (int j = 0; j < 16; j++) m = fmaxf(m, acc[i][j]);
        #pragma unroll
        for (int o = 16; o >= 1; o >>= 1)
            m = fmaxf(m, __shfl_xor_sync(0xffffffffu, m, o));

        // bitmap words needed by this lane: word index = g*4 + (tx>>3)
        unsigned wbits[4];
        #pragma unroll
        for (int g = 0; g < 4; g++)
            wbits[g] = g_maskbits[r * NWORDS + g * 4 + (tx >> 3)];

        float e[16];
        float z = 0.f, amask = 0.f;
        #pragma unroll
        for (int g = 0; g < 4; g++) {
            #pragma unroll
            for (int j = 0; j < 4; j++) {
                float ev = expf(acc[i][g * 4 + j] - m);
                e[g * 4 + j] = ev;
                z += ev;
                if ((wbits[g] >> (((tx & 7) << 2) + j)) & 1u) amask += ev;
            }
        }
        #pragma unroll
        for (int o = 16; o >= 1; o >>= 1) {
            z     += __shfl_xor_sync(0xffffffffu, z, o);
            amask += __shfl_xor_sync(0xffffffffu, amask, o);
        }

        // scores = e_v / (A_e + eps*(Z - A_e)) at set bits, else exactly 0
        const float denom = amask + 1e-10f * (z - amask);
        const float inv   = 1.0f / denom;

        #pragma unroll
        for (int g = 0; g < 4; g++) {
            float4 ov;
            float* ovp = (float*)&ov;
            #pragma unroll
            for (int j = 0; j < 4; j++) {
                bool set = (wbits[g] >> (((tx & 7) << 2) + j)) & 1u;
                ovp[j] = set ? e[g * 4 + j] * inv : 0.f;
            }
            *(float4*)&out[(size_t)r * SEQ + tx * 4 + g * 128] = ov;
        }
    }
}

extern "C" void kernel_launch(void* const* d_in, const int* in_sizes, int n_in,
                              void* d_out, int out_size) {
    const float* M  = (const float*)d_in[0];   // (512, 64, 512) f32
    const float* W  = (const float*)d_in[1];   // (512, 512) f32
    // d_in[2] = lengths (unused by the reference)
    const int*   eb = (const int*)d_in[3];
    const int*   eu = (const int*)d_in[4];
    const int*   ev = (const int*)d_in[5];
    const int    E  = in_sizes[3];
    float* out = (float*)d_out;                // (64, 512, 512) f32

    const int maskWords = BATCH * MAXLEN * NWORDS;
    clear_mask_kernel<<<(maskWords + 255) / 256, 256>>>();
    build_mask_kernel<<<(E + 255) / 256, 256>>>(eb, eu, ev, E);
    gemm_softmax_kernel<<<dim3(MAXLEN / 32, BATCH), 256>>>(M, W, out);
}

// round 5
// speedup vs baseline: 2.1333x; 2.1333x over previous
#include <cuda_runtime.h>
#include <cuda_bf16.h>
#include <cstdint>

#define SEQ    512
#define BATCH  64
#define DIM    512
#define MAXLEN 512
#define NWORDS (SEQ/32)

#define UTILE   64           // u rows per CTA
#define KCHUNK  64           // bf16 elems per smem row = 128 bytes (SW128)
#define NCHUNKS (DIM/KCHUNK) // 8
#define KSTEPS  (KCHUNK/16)  // 4

// ---- SMEM layout (bytes) ----
#define SM_AHI   0
#define SM_ALO   (SM_AHI + UTILE*128)          // 8192
#define SM_BHI   (SM_ALO + UTILE*128)          // 16384
#define SM_BLO   (SM_BHI + SEQ*128)            // 81920
#define SM_TOTAL (SM_BLO + SEQ*128)            // 147456

// 2 MB bitmap: bit v of row (b*MAXLEN+u) set iff some edge hits (b,u,v).
__device__ unsigned g_maskbits[BATCH * MAXLEN * NWORDS];

__global__ void clear_mask_kernel() {
    int i = blockIdx.x * blockDim.x + threadIdx.x;
    if (i < BATCH * MAXLEN * NWORDS) g_maskbits[i] = 0u;
}

__global__ void build_mask_kernel(const int* __restrict__ eb,
                                  const int* __restrict__ eu,
                                  const int* __restrict__ ev, int E) {
    int i = blockIdx.x * blockDim.x + threadIdx.x;
    if (i >= E) return;
    atomicOr(&g_maskbits[(eb[i] * MAXLEN + eu[i]) * NWORDS + (ev[i] >> 5)],
             1u << (ev[i] & 31));
}

// ---------------- helpers ----------------
__device__ __forceinline__ uint32_t smem_u32(const void* p) {
    uint32_t a;
    asm("{ .reg .u64 t; cvta.to.shared.u64 t, %1; cvt.u32.u64 %0, t; }" : "=r"(a) : "l"(p));
    return a;
}
__device__ __forceinline__ uint32_t sw128(uint32_t off) { return off ^ ((off >> 3) & 0x70); }

__device__ __forceinline__ void ldsm_x4(uint32_t& r0, uint32_t& r1,
                                        uint32_t& r2, uint32_t& r3, uint32_t addr) {
    asm volatile("ldmatrix.sync.aligned.m8n8.x4.shared.b16 {%0,%1,%2,%3}, [%4];"
                 : "=r"(r0), "=r"(r1), "=r"(r2), "=r"(r3) : "r"(addr));
}

__device__ __forceinline__ void mma16816(float* d, const uint32_t* a,
                                         uint32_t b0, uint32_t b1) {
    asm volatile("mma.sync.aligned.m16n8k16.row.col.f32.bf16.bf16.f32 "
                 "{%0,%1,%2,%3}, {%4,%5,%6,%7}, {%8,%9}, {%0,%1,%2,%3};"
                 : "+f"(d[0]), "+f"(d[1]), "+f"(d[2]), "+f"(d[3])
                 : "r"(a[0]), "r"(a[1]), "r"(a[2]), "r"(a[3]), "r"(b0), "r"(b1));
}

// split fp32 float4 -> 4 hi bf16 + 4 lo bf16 packed as uint2 each
__device__ __forceinline__ void split4(float4 v, uint2& hi, uint2& lo) {
    __nv_bfloat16 hx = __float2bfloat16_rn(v.x);
    __nv_bfloat16 hy = __float2bfloat16_rn(v.y);
    __nv_bfloat16 hz = __float2bfloat16_rn(v.z);
    __nv_bfloat16 hw = __float2bfloat16_rn(v.w);
    __nv_bfloat16 lx = __float2bfloat16_rn(v.x - __bfloat162float(hx));
    __nv_bfloat16 ly = __float2bfloat16_rn(v.y - __bfloat162float(hy));
    __nv_bfloat16 lz = __float2bfloat16_rn(v.z - __bfloat162float(hz));
    __nv_bfloat16 lw = __float2bfloat16_rn(v.w - __bfloat162float(hw));
    __nv_bfloat162 h01 = __halves2bfloat162(hx, hy), h23 = __halves2bfloat162(hz, hw);
    __nv_bfloat162 l01 = __halves2bfloat162(lx, ly), l23 = __halves2bfloat162(lz, lw);
    hi.x = *(uint32_t*)&h01; hi.y = *(uint32_t*)&h23;
    lo.x = *(uint32_t*)&l01; lo.y = *(uint32_t*)&l23;
}

__global__ __launch_bounds__(512, 1)
void mea_mma_kernel(const float* __restrict__ Mm,   // (SEQ, BATCH, DIM)
                    const float* __restrict__ Wm,   // (MAXLEN, DIM)
                    float* __restrict__ out) {      // (BATCH, MAXLEN, SEQ)
    extern __shared__ char smem[];
    const uint32_t sb = smem_u32(smem);
    const int tid  = threadIdx.x;
    const int wid  = tid >> 5;
    const int lane = tid & 31;
    const int wu   = wid >> 2;      // 0..3 : u-slice (16 rows)
    const int ws   = wid & 3;       // 0..3 : s-slice (128 cols)
    const int b     = blockIdx.y;
    const int utile = blockIdx.x * UTILE;

    // Per-lane ldmatrix address components (SW128, 128B rows).
    const int xr       = (lane & 7) << 4;            // swizzle XOR for both A and B
    const int a_rowoff = (lane & 15) * 128;          // A: rows u0 + (lane&15)
    const int a_kh     = (lane >> 4) * 16;           // A: +16B for k-hi half
    const int b_rowl   = ((lane >> 4) << 3) + (lane & 7);
    const int b_kh     = ((lane >> 3) & 1) << 4;
    const uint32_t aBaseHi = sb + SM_AHI + wu * 16 * 128 + a_rowoff;
    const uint32_t aBaseLo = sb + SM_ALO + wu * 16 * 128 + a_rowoff;
    const uint32_t bBaseHi = sb + SM_BHI + (ws * 128 + b_rowl) * 128;
    const uint32_t bBaseLo = sb + SM_BLO + (ws * 128 + b_rowl) * 128;

    float acc[16][4];
    #pragma unroll
    for (int nt = 0; nt < 16; nt++)
        #pragma unroll
        for (int j = 0; j < 4; j++) acc[nt][j] = 0.f;

    for (int ck = 0; ck < NCHUNKS; ck++) {
        const int kt = ck * KCHUNK;
        // B tile: M[s, b, kt..kt+63] -> 512 rows x 128B (hi & lo)
        #pragma unroll
        for (int it = 0; it < 16; it++) {
            int idx = it * 512 + tid;
            int s = idx >> 4, f4 = idx & 15;
            float4 v = *(const float4*)&Mm[((size_t)s * BATCH + b) * DIM + kt + f4 * 4];
            uint2 hi, lo; split4(v, hi, lo);
            uint32_t off = sw128((uint32_t)(s * 128 + f4 * 8));
            *(uint2*)(smem + SM_BHI + off) = hi;
            *(uint2*)(smem + SM_BLO + off) = lo;
        }
        // A tile: W[utile+u, kt..kt+63] -> 64 rows x 128B
        #pragma unroll
        for (int it = 0; it < 2; it++) {
            int idx = it * 512 + tid;
            int u = idx >> 4, f4 = idx & 15;
            float4 v = *(const float4*)&Wm[(size_t)(utile + u) * DIM + kt + f4 * 4];
            uint2 hi, lo; split4(v, hi, lo);
            uint32_t off = sw128((uint32_t)(u * 128 + f4 * 8));
            *(uint2*)(smem + SM_AHI + off) = hi;
            *(uint2*)(smem + SM_ALO + off) = lo;
        }
        __syncthreads();

        #pragma unroll
        for (int ks = 0; ks < KSTEPS; ks++) {
            const uint32_t akc = (uint32_t)((ks * 32 + a_kh) ^ xr);
            const uint32_t bkc = (uint32_t)((ks * 32 + b_kh) ^ xr);
            uint32_t ah[4], al[4];
            ldsm_x4(ah[0], ah[1], ah[2], ah[3], aBaseHi + akc);
            ldsm_x4(al[0], al[1], al[2], al[3], aBaseLo + akc);
            #pragma unroll
            for (int np = 0; np < 8; np++) {
                uint32_t b0, b1, b2, b3;
                ldsm_x4(b0, b1, b2, b3, bBaseHi + np * 16 * 128 + bkc);
                mma16816(acc[2*np+0], ah, b0, b1);
                mma16816(acc[2*np+1], ah, b2, b3);
                mma16816(acc[2*np+0], al, b0, b1);
                mma16816(acc[2*np+1], al, b2, b3);
                ldsm_x4(b0, b1, b2, b3, bBaseLo + np * 16 * 128 + bkc);
                mma16816(acc[2*np+0], ah, b0, b1);
                mma16816(acc[2*np+1], ah, b2, b3);
            }
        }
        __syncthreads();
    }

    // ---------------- epilogue ----------------
    // Acc frag: thread owns rows rl0 = lane/4 and rl0+8 (of warp's 16),
    // cols s = ws*128 + nt*8 + 2*(lane&3) + {0,1}.
    const int rl0 = lane >> 2;
    const int tig = lane & 3;
    const int ul0 = wu * 16 + rl0;         // local u 0..63
    const int ul1 = ul0 + 8;
    const int r0  = b * MAXLEN + utile + ul0;
    const int r1  = b * MAXLEN + utile + ul1;

    unsigned w0[4], w1[4];
    #pragma unroll
    for (int q = 0; q < 4; q++) {
        w0[q] = g_maskbits[r0 * NWORDS + ws * 4 + q];
        w1[q] = g_maskbits[r1 * NWORDS + ws * 4 + q];
    }

    float z0 = 0.f, am0 = 0.f, z1 = 0.f, am1 = 0.f;
    #pragma unroll
    for (int nt = 0; nt < 16; nt++) {
        const int q   = nt >> 2;
        const int bit = (nt & 3) * 8 + 2 * tig;
        float e0 = __expf(acc[nt][0]);
        float e1 = __expf(acc[nt][1]);
        float e2 = __expf(acc[nt][2]);
        float e3 = __expf(acc[nt][3]);
        acc[nt][0] = e0; acc[nt][1] = e1; acc[nt][2] = e2; acc[nt][3] = e3;
        z0 += e0 + e1; z1 += e2 + e3;
        if ((w0[q] >> bit)       & 1u) am0 += e0;
        if ((w0[q] >> (bit + 1)) & 1u) am0 += e1;
        if ((w1[q] >> bit)       & 1u) am1 += e2;
        if ((w1[q] >> (bit + 1)) & 1u) am1 += e3;
    }
    // reduce over the 4 lanes sharing each row (t%4 varies -> xor 1,2)
    #pragma unroll
    for (int o = 1; o <= 2; o <<= 1) {
        z0  += __shfl_xor_sync(0xffffffffu, z0,  o);
        am0 += __shfl_xor_sync(0xffffffffu, am0, o);
        z1  += __shfl_xor_sync(0xffffffffu, z1,  o);
        am1 += __shfl_xor_sync(0xffffffffu, am1, o);
    }

    // cross-warp (ws) reduction via smem partials, fixed-order sum
    float* red = (float*)smem;   // z: [0,256), am: [256,512)
    if (tig == 0) {
        red[ws * 64 + ul0]       = z0;
        red[ws * 64 + ul1]       = z1;
        red[256 + ws * 64 + ul0] = am0;
        red[256 + ws * 64 + ul1] = am1;
    }
    __syncthreads();
    float zs0 = 0.f, as0 = 0.f, zs1 = 0.f, as1 = 0.f;
    #pragma unroll
    for (int w = 0; w < 4; w++) {
        zs0 += red[w * 64 + ul0];       as0 += red[256 + w * 64 + ul0];
        zs1 += red[w * 64 + ul1];       as1 += red[256 + w * 64 + ul1];
    }
    const float inv0 = 1.0f / (as0 + 1e-10f * (zs0 - as0));
    const float inv1 = 1.0f / (as1 + 1e-10f * (zs1 - as1));

    #pragma unroll
    for (int nt = 0; nt < 16; nt++) {
        const int q   = nt >> 2;
        const int bit = (nt & 3) * 8 + 2 * tig;
        const int sc  = ws * 128 + nt * 8 + 2 * tig;
        float2 v0, v1;
        v0.x = ((w0[q] >> bit)       & 1u) ? acc[nt][0] * inv0 : 0.f;
        v0.y = ((w0[q] >> (bit + 1)) & 1u) ? acc[nt][1] * inv0 : 0.f;
        v1.x = ((w1[q] >> bit)       & 1u) ? acc[nt][2] * inv1 : 0.f;
        v1.y = ((w1[q] >> (bit + 1)) & 1u) ? acc[nt][3] * inv1 : 0.f;
        *(float2*)&out[(size_t)r0 * SEQ + sc] = v0;
        *(float2*)&out[(size_t)r1 * SEQ + sc] = v1;
    }
}

extern "C" void kernel_launch(void* const* d_in, const int* in_sizes, int n_in,
                              void* d_out, int out_size) {
    const float* M  = (const float*)d_in[0];
    const float* W  = (const float*)d_in[1];
    const int*   eb = (const int*)d_in[3];
    const int*   eu = (const int*)d_in[4];
    const int*   ev = (const int*)d_in[5];
    const int    E  = in_sizes[3];
    float* out = (float*)d_out;

    cudaFuncSetAttribute(mea_mma_kernel,
                         cudaFuncAttributeMaxDynamicSharedMemorySize, SM_TOTAL);

    const int maskWords = BATCH * MAXLEN * NWORDS;
    clear_mask_kernel<<<(maskWords + 255) / 256, 256>>>();
    build_mask_kernel<<<(E + 255) / 256, 256>>>(eb, eu, ev, E);
    mea_mma_kernel<<<dim3(MAXLEN / UTILE, BATCH), 512, SM_TOTAL>>>(M, W, out);
}